// round 11
// baseline (speedup 1.0000x reference)
#include <cuda_runtime.h>
#include <math.h>
#include <stdint.h>

#define MAX_ROWS    32768
#define HSZ         32768                 // hash table slots (power of 2)
#define MAX_BBLK    (MAX_ROWS / 256)      // build-kernel blocks
#define MAX_PBLK    64                    // probe-kernel blocks
#define PIN_ROWS    6144                  // rows read with evict-normal (~96MB
                                          // of gt kept L2-resident across graph
                                          // replays; rest streams evict-first)

// ---------------- device scratch (no allocations allowed) ----------------
__device__ float g_rowsum[MAX_ROWS];
__device__ int   g_jfirst[MAX_ROWS];
__device__ int   g_head[HSZ];
__device__ int   g_next[MAX_ROWS];
__device__ float g_csum[MAX_BBLK];
__device__ int   g_vany[MAX_BBLK];
__device__ float g_msum[MAX_PBLK];
__device__ int   g_mcnt[MAX_PBLK];

__device__ __forceinline__ uint32_t hash_x(float x) {
    uint32_t u = __float_as_uint(x) * 2654435761u;
    return (u >> 17) & (HSZ - 1);         // top 15 bits
}

// Row body templated on load policy: PIN -> __ldcg (L2 evict-normal, persists
// across graph replays), else __ldcs (evict-first, streams through).
template <bool PIN>
__device__ __forceinline__ void row_body(
    const float* __restrict__ cr, const float* __restrict__ gr,
    const float4* __restrict__ g4, int nv, int L,
    float& lsum, int& lmin)
{
    int v0 = 0;
    for (; v0 + 1024 <= nv; v0 += 1024) {
        float4 r[8];
        #pragma unroll
        for (int i = 0; i < 8; i++) {
            const float4* p = &g4[v0 + threadIdx.x + i * 128];
            r[i] = PIN ? __ldcg(p) : __ldcs(p);
        }
        #pragma unroll
        for (int i = 0; i < 8; i++) {
            const float4 g = r[i];
            if (g.x != 0.0f || g.y != 0.0f || g.z != 0.0f || g.w != 0.0f) {
                const int j = (v0 + threadIdx.x + i * 128) << 2;
                if (g.x != 0.0f) lsum += g.x * __logf(cr[j + 0] + 1e-6f);
                if (g.y != 0.0f) lsum += g.y * __logf(cr[j + 1] + 1e-6f);
                if (g.z != 0.0f) lsum += g.z * __logf(cr[j + 2] + 1e-6f);
                if (g.w != 0.0f) lsum += g.w * __logf(cr[j + 3] + 1e-6f);
                if      (g.x > 0.0f) lmin = min(lmin, j + 0);
                else if (g.y > 0.0f) lmin = min(lmin, j + 1);
                else if (g.z > 0.0f) lmin = min(lmin, j + 2);
                else if (g.w > 0.0f) lmin = min(lmin, j + 3);
            }
        }
    }
    for (int v = v0 + threadIdx.x; v < nv; v += 128) {
        const float4* p = &g4[v];
        const float4 g = PIN ? __ldcg(p) : __ldcs(p);
        if (g.x != 0.0f || g.y != 0.0f || g.z != 0.0f || g.w != 0.0f) {
            const int j = v << 2;
            if (g.x != 0.0f) lsum += g.x * __logf(cr[j + 0] + 1e-6f);
            if (g.y != 0.0f) lsum += g.y * __logf(cr[j + 1] + 1e-6f);
            if (g.z != 0.0f) lsum += g.z * __logf(cr[j + 2] + 1e-6f);
            if (g.w != 0.0f) lsum += g.w * __logf(cr[j + 3] + 1e-6f);
            if      (g.x > 0.0f) lmin = min(lmin, j + 0);
            else if (g.y > 0.0f) lmin = min(lmin, j + 1);
            else if (g.z > 0.0f) lmin = min(lmin, j + 2);
            else if (g.w > 0.0f) lmin = min(lmin, j + 3);
        }
    }
    for (int j = (nv << 2) + threadIdx.x; j < L; j += 128) {
        const float g = gr[j];
        if (g != 0.0f) lsum += g * __logf(cr[j] + 1e-6f);
        if (g > 0.0f)  lmin = min(lmin, j);
    }
}

// ---------------- kernel 1: one block (128 thr) per row of [B*L, L] -------
__global__ void __launch_bounds__(128) mc_row_kernel(
    const float* __restrict__ cm,
    const float* __restrict__ gt,
    int L)
{
    for (int i = blockIdx.x * 128 + threadIdx.x; i < HSZ; i += gridDim.x * 128)
        g_head[i] = -1;

    const int row = blockIdx.x;
    const long long base = (long long)row * (long long)L;
    const float*  gr = gt + base;
    const float*  cr = cm + base;
    const float4* g4 = (const float4*)gr;
    const int nv = L >> 2;

    float lsum = 0.0f;
    int   lmin = 0x7fffffff;

    if (row < PIN_ROWS) row_body<true >(cr, gr, g4, nv, L, lsum, lmin);
    else                row_body<false>(cr, gr, g4, nv, L, lsum, lmin);

    #pragma unroll
    for (int o = 16; o > 0; o >>= 1) {
        lsum += __shfl_down_sync(0xffffffffu, lsum, o);
        lmin  = min(lmin, __shfl_down_sync(0xffffffffu, lmin, o));
    }
    __shared__ float ws[4];
    __shared__ int   wm[4];
    const int wid = threadIdx.x >> 5;
    if ((threadIdx.x & 31) == 0) { ws[wid] = lsum; wm[wid] = lmin; }
    __syncthreads();
    if (threadIdx.x == 0) {
        lsum = ws[0] + ws[1] + ws[2] + ws[3];
        lmin = min(min(wm[0], wm[1]), min(wm[2], wm[3]));
        g_rowsum[row] = lsum;
        g_jfirst[row] = (lmin < 0x7fffffff) ? lmin : -1;
    }
}

// ---------------- kernel 2: hash build + coarse partial reduce -------------
__global__ void __launch_bounds__(256) mc_build_kernel(
    const float* __restrict__ samples0, int rows)
{
    const int tid = threadIdx.x;
    const int r = blockIdx.x * 256 + tid;

    float cs = 0.0f;
    int   va = 0;
    if (r < rows) {
        cs = g_rowsum[r];
        const int jf = g_jfirst[r];
        va = (jf >= 0);
        if (va) {
            const float x = ((const float2*)samples0)[r].x;
            g_next[r] = atomicExch(&g_head[hash_x(x)], r);
        }
    }

    #pragma unroll
    for (int o = 16; o > 0; o >>= 1) {
        cs += __shfl_down_sync(0xffffffffu, cs, o);
        va |= __shfl_down_sync(0xffffffffu, va, o);
    }
    __shared__ float wcs[8];
    __shared__ int   wva[8];
    const int wid = tid >> 5;
    if ((tid & 31) == 0) { wcs[wid] = cs; wva[wid] = va; }
    __syncthreads();
    if (tid == 0) {
        cs = 0.0f; va = 0;
        #pragma unroll
        for (int i = 0; i < 8; i++) { cs += wcs[i]; va |= wva[i]; }
        g_csum[blockIdx.x] = cs;
        g_vany[blockIdx.x] = va;
    }
}

// ---------------- kernel 3: probe (one thread per predicted point) --------
__global__ void __launch_bounds__(256) mc_probe_kernel(
    const float* __restrict__ samples0,
    const float* __restrict__ samples1,
    const float* __restrict__ mkpts0,
    const float* __restrict__ mkpts1,
    int L, int N)
{
    const int tid = threadIdx.x;
    const int n = blockIdx.x * 256 + tid;

    float fs = 0.0f;
    int   fc = 0;
    if (n < N) {
        const float bf = mkpts0[3 * n + 0];
        const float x  = mkpts0[3 * n + 1];
        const float y  = mkpts0[3 * n + 2];
        const float2* s0 = (const float2*)samples0;

        int best = 0x7fffffff;
        for (int r = g_head[hash_x(x)]; r >= 0; r = g_next[r]) {
            const float2 p = s0[r];
            if (p.x == x && p.y == y && (float)(r / L) == bf)
                best = min(best, r);
        }
        if (best != 0x7fffffff) {
            const int jf = g_jfirst[best];
            const int b  = best / L;
            const float2 q = ((const float2*)samples1)[(long long)b * L + jf];
            const float dx = q.x - mkpts1[2 * n + 0];
            const float dy = q.y - mkpts1[2 * n + 1];
            const float nrm = sqrtf(dx * dx + dy * dy);
            if (nrm < 10.0f) { fs = nrm; fc = 1; }
        }
    }

    #pragma unroll
    for (int o = 16; o > 0; o >>= 1) {
        fs += __shfl_down_sync(0xffffffffu, fs, o);
        fc += __shfl_down_sync(0xffffffffu, fc, o);
    }
    __shared__ float wfs[8];
    __shared__ int   wfc[8];
    const int wid = tid >> 5;
    if ((tid & 31) == 0) { wfs[wid] = fs; wfc[wid] = fc; }
    __syncthreads();
    if (tid == 0) {
        fs = 0.0f; fc = 0;
        #pragma unroll
        for (int i = 0; i < 8; i++) { fs += wfs[i]; fc += wfc[i]; }
        g_msum[blockIdx.x] = fs;
        g_mcnt[blockIdx.x] = fc;
    }
}

// ---------------- kernel 4: finalize ----------------
__global__ void __launch_bounds__(128) mc_finalize_kernel(
    float* __restrict__ out, int nb, int pb, float Bf)
{
    const int tid = threadIdx.x;
    float cs = 0.0f, fs = 0.0f;
    int   va = 0,    fc = 0;
    for (int i = tid; i < nb; i += 128) { cs += g_csum[i]; va |= g_vany[i]; }
    for (int i = tid; i < pb; i += 128) { fs += g_msum[i]; fc += g_mcnt[i]; }

    #pragma unroll
    for (int o = 16; o > 0; o >>= 1) {
        cs += __shfl_down_sync(0xffffffffu, cs, o);
        fs += __shfl_down_sync(0xffffffffu, fs, o);
        fc += __shfl_down_sync(0xffffffffu, fc, o);
        va |= __shfl_down_sync(0xffffffffu, va, o);
    }
    __shared__ float wcs[4], wfs[4];
    __shared__ int   wfc[4], wva[4];
    const int wid = tid >> 5;
    if ((tid & 31) == 0) { wcs[wid] = cs; wfs[wid] = fs; wfc[wid] = fc; wva[wid] = va; }
    __syncthreads();
    if (tid == 0) {
        cs = wcs[0] + wcs[1] + wcs[2] + wcs[3];
        fs = wfs[0] + wfs[1] + wfs[2] + wfs[3];
        fc = wfc[0] + wfc[1] + wfc[2] + wfc[3];
        va = wva[0] | wva[1] | wva[2] | wva[3];
        const float coarse = -cs / Bf;
        float fine;
        if (va) fine = (fc > 0) ? (fs / (float)fc) : 10.0f;
        else    fine = 1e-6f;
        out[0] = coarse + 1000.0f * fine;
        out[1] = coarse;
        out[2] = fine;
    }
}

extern "C" void kernel_launch(void* const* d_in, const int* in_sizes, int n_in,
                              void* d_out, int out_size)
{
    const float* cm       = (const float*)d_in[0];  // [B,L,L]
    const float* gt       = (const float*)d_in[1];  // [B,L,L]
    const float* samples0 = (const float*)d_in[2];  // [B,L,2]
    const float* samples1 = (const float*)d_in[3];  // [B,L,2]
    const float* mkpts0   = (const float*)d_in[4];  // [N,3]
    const float* mkpts1   = (const float*)d_in[5];  // [N,2]
    float* out = (float*)d_out;

    const long long BL = (long long)in_sizes[2] / 2;       // B*L
    const int L = (int)((long long)in_sizes[0] / BL);      // B*L*L / (B*L)
    const int B = (int)(BL / L);
    const int N = in_sizes[4] / 3;
    const int rows = B * L;
    const int nb = (rows + 255) / 256;   // build blocks
    const int pb = (N + 255) / 256;      // probe blocks

    mc_row_kernel<<<rows, 128>>>(cm, gt, L);
    mc_build_kernel<<<nb, 256>>>(samples0, rows);
    mc_probe_kernel<<<pb, 256>>>(samples0, samples1, mkpts0, mkpts1, L, N);
    mc_finalize_kernel<<<1, 128>>>(out, nb, pb, (float)B);
}

// round 12
// speedup vs baseline: 1.1153x; 1.1153x over previous
#include <cuda_runtime.h>
#include <math.h>
#include <stdint.h>

#define MAX_ROWS    32768
#define HSZ         32768                 // hash table slots (power of 2)
#define MAX_BBLK    (MAX_ROWS / 256)      // build-kernel blocks
#define MAX_PBLK    64                    // probe-kernel blocks

// ---------------- device scratch (no allocations allowed) ----------------
__device__ float g_rowsum[MAX_ROWS];
__device__ int   g_jfirst[MAX_ROWS];
__device__ int   g_head[HSZ];
__device__ int   g_next[MAX_ROWS];
__device__ float g_csum[MAX_BBLK];
__device__ int   g_vany[MAX_BBLK];
__device__ float g_msum[MAX_PBLK];
__device__ int   g_mcnt[MAX_PBLK];

__device__ __forceinline__ uint32_t hash_x(float x) {
    uint32_t u = __float_as_uint(x) * 2654435761u;
    return (u >> 17) & (HSZ - 1);         // top 15 bits
}

// PDL primitives (sm_90+): dependent grids pre-launch; wait blocks until the
// upstream grid's writes are visible.
__device__ __forceinline__ void gdc_wait()   { asm volatile("griddepcontrol.wait;" ::: "memory"); }
__device__ __forceinline__ void gdc_launch() { asm volatile("griddepcontrol.launch_dependents;"); }

// ---------------- kernel 1: one block (128 thr) per row of [B*L, L] -------
// PROVEN 45.9us stream (R2/R3): gt via __ldcs, cm gathered only where gt!=0,
// first j with gt>0, hash-head reset interleaved.
__global__ void __launch_bounds__(128) mc_row_kernel(
    const float* __restrict__ cm,
    const float* __restrict__ gt,
    int L)
{
    for (int i = blockIdx.x * 128 + threadIdx.x; i < HSZ; i += gridDim.x * 128)
        g_head[i] = -1;

    const int row = blockIdx.x;
    const long long base = (long long)row * (long long)L;
    const float*  gr = gt + base;
    const float*  cr = cm + base;
    const float4* g4 = (const float4*)gr;
    const int nv = L >> 2;

    float lsum = 0.0f;
    int   lmin = 0x7fffffff;

    int v0 = 0;
    for (; v0 + 1024 <= nv; v0 += 1024) {
        float4 r[8];
        #pragma unroll
        for (int i = 0; i < 8; i++)
            r[i] = __ldcs(&g4[v0 + threadIdx.x + i * 128]);
        #pragma unroll
        for (int i = 0; i < 8; i++) {
            const float4 g = r[i];
            if (g.x != 0.0f || g.y != 0.0f || g.z != 0.0f || g.w != 0.0f) {
                const int j = (v0 + threadIdx.x + i * 128) << 2;
                if (g.x != 0.0f) lsum += g.x * __logf(cr[j + 0] + 1e-6f);
                if (g.y != 0.0f) lsum += g.y * __logf(cr[j + 1] + 1e-6f);
                if (g.z != 0.0f) lsum += g.z * __logf(cr[j + 2] + 1e-6f);
                if (g.w != 0.0f) lsum += g.w * __logf(cr[j + 3] + 1e-6f);
                if      (g.x > 0.0f) lmin = min(lmin, j + 0);
                else if (g.y > 0.0f) lmin = min(lmin, j + 1);
                else if (g.z > 0.0f) lmin = min(lmin, j + 2);
                else if (g.w > 0.0f) lmin = min(lmin, j + 3);
            }
        }
    }
    for (int v = v0 + threadIdx.x; v < nv; v += 128) {
        const float4 g = __ldcs(&g4[v]);
        if (g.x != 0.0f || g.y != 0.0f || g.z != 0.0f || g.w != 0.0f) {
            const int j = v << 2;
            if (g.x != 0.0f) lsum += g.x * __logf(cr[j + 0] + 1e-6f);
            if (g.y != 0.0f) lsum += g.y * __logf(cr[j + 1] + 1e-6f);
            if (g.z != 0.0f) lsum += g.z * __logf(cr[j + 2] + 1e-6f);
            if (g.w != 0.0f) lsum += g.w * __logf(cr[j + 3] + 1e-6f);
            if      (g.x > 0.0f) lmin = min(lmin, j + 0);
            else if (g.y > 0.0f) lmin = min(lmin, j + 1);
            else if (g.z > 0.0f) lmin = min(lmin, j + 2);
            else if (g.w > 0.0f) lmin = min(lmin, j + 3);
        }
    }
    for (int j = (nv << 2) + threadIdx.x; j < L; j += 128) {
        const float g = gr[j];
        if (g != 0.0f) lsum += g * __logf(cr[j] + 1e-6f);
        if (g > 0.0f)  lmin = min(lmin, j);
    }

    #pragma unroll
    for (int o = 16; o > 0; o >>= 1) {
        lsum += __shfl_down_sync(0xffffffffu, lsum, o);
        lmin  = min(lmin, __shfl_down_sync(0xffffffffu, lmin, o));
    }
    __shared__ float ws[4];
    __shared__ int   wm[4];
    const int wid = threadIdx.x >> 5;
    if ((threadIdx.x & 31) == 0) { ws[wid] = lsum; wm[wid] = lmin; }
    __syncthreads();
    if (threadIdx.x == 0) {
        lsum = ws[0] + ws[1] + ws[2] + ws[3];
        lmin = min(min(wm[0], wm[1]), min(wm[2], wm[3]));
        g_rowsum[row] = lsum;
        g_jfirst[row] = (lmin < 0x7fffffff) ? lmin : -1;
    }
    __syncthreads();          // all stores precede this CTA's trigger
    gdc_launch();             // permit dependent (build) to pre-launch
}

// ---------------- kernel 2: hash build + coarse partial reduce -------------
__global__ void __launch_bounds__(256) mc_build_kernel(
    const float* __restrict__ samples0, int rows)
{
    const int tid = threadIdx.x;
    const int r = blockIdx.x * 256 + tid;

    // independent input load BEFORE the dependency wait (overlaps upstream tail)
    float x = 0.0f;
    if (r < rows) x = ((const float2*)samples0)[r].x;

    gdc_wait();               // row-kernel writes now visible
    gdc_launch();             // permit probe to pre-launch

    float cs = 0.0f;
    int   va = 0;
    if (r < rows) {
        cs = g_rowsum[r];
        const int jf = g_jfirst[r];
        va = (jf >= 0);
        if (va)
            g_next[r] = atomicExch(&g_head[hash_x(x)], r);
    }

    #pragma unroll
    for (int o = 16; o > 0; o >>= 1) {
        cs += __shfl_down_sync(0xffffffffu, cs, o);
        va |= __shfl_down_sync(0xffffffffu, va, o);
    }
    __shared__ float wcs[8];
    __shared__ int   wva[8];
    const int wid = tid >> 5;
    if ((tid & 31) == 0) { wcs[wid] = cs; wva[wid] = va; }
    __syncthreads();
    if (tid == 0) {
        cs = 0.0f; va = 0;
        #pragma unroll
        for (int i = 0; i < 8; i++) { cs += wcs[i]; va |= wva[i]; }
        g_csum[blockIdx.x] = cs;
        g_vany[blockIdx.x] = va;
    }
}

// ---------------- kernel 3: probe (one thread per predicted point) --------
__global__ void __launch_bounds__(256) mc_probe_kernel(
    const float* __restrict__ samples0,
    const float* __restrict__ samples1,
    const float* __restrict__ mkpts0,
    const float* __restrict__ mkpts1,
    int L, int N)
{
    const int tid = threadIdx.x;
    const int n = blockIdx.x * 256 + tid;

    // independent input loads BEFORE the dependency wait
    float bf = 0.0f, x = 0.0f, y = 0.0f, m1x = 0.0f, m1y = 0.0f;
    if (n < N) {
        bf  = mkpts0[3 * n + 0];
        x   = mkpts0[3 * n + 1];
        y   = mkpts0[3 * n + 2];
        m1x = mkpts1[2 * n + 0];
        m1y = mkpts1[2 * n + 1];
    }

    gdc_wait();               // build-kernel hash now visible
    gdc_launch();             // permit finalize to pre-launch

    float fs = 0.0f;
    int   fc = 0;
    if (n < N) {
        const float2* s0 = (const float2*)samples0;
        int best = 0x7fffffff;
        for (int r = g_head[hash_x(x)]; r >= 0; r = g_next[r]) {
            const float2 p = s0[r];
            if (p.x == x && p.y == y && (float)(r / L) == bf)
                best = min(best, r);
        }
        if (best != 0x7fffffff) {
            const int jf = g_jfirst[best];
            const int b  = best / L;
            const float2 q = ((const float2*)samples1)[(long long)b * L + jf];
            const float dx = q.x - m1x;
            const float dy = q.y - m1y;
            const float nrm = sqrtf(dx * dx + dy * dy);
            if (nrm < 10.0f) { fs = nrm; fc = 1; }
        }
    }

    #pragma unroll
    for (int o = 16; o > 0; o >>= 1) {
        fs += __shfl_down_sync(0xffffffffu, fs, o);
        fc += __shfl_down_sync(0xffffffffu, fc, o);
    }
    __shared__ float wfs[8];
    __shared__ int   wfc[8];
    const int wid = tid >> 5;
    if ((tid & 31) == 0) { wfs[wid] = fs; wfc[wid] = fc; }
    __syncthreads();
    if (tid == 0) {
        fs = 0.0f; fc = 0;
        #pragma unroll
        for (int i = 0; i < 8; i++) { fs += wfs[i]; fc += wfc[i]; }
        g_msum[blockIdx.x] = fs;
        g_mcnt[blockIdx.x] = fc;
    }
}

// ---------------- kernel 4: finalize ----------------
__global__ void __launch_bounds__(128) mc_finalize_kernel(
    float* __restrict__ out, int nb, int pb, float Bf)
{
    gdc_wait();               // probe partials now visible

    const int tid = threadIdx.x;
    float cs = 0.0f, fs = 0.0f;
    int   va = 0,    fc = 0;
    for (int i = tid; i < nb; i += 128) { cs += g_csum[i]; va |= g_vany[i]; }
    for (int i = tid; i < pb; i += 128) { fs += g_msum[i]; fc += g_mcnt[i]; }

    #pragma unroll
    for (int o = 16; o > 0; o >>= 1) {
        cs += __shfl_down_sync(0xffffffffu, cs, o);
        fs += __shfl_down_sync(0xffffffffu, fs, o);
        fc += __shfl_down_sync(0xffffffffu, fc, o);
        va |= __shfl_down_sync(0xffffffffu, va, o);
    }
    __shared__ float wcs[4], wfs[4];
    __shared__ int   wfc[4], wva[4];
    const int wid = tid >> 5;
    if ((tid & 31) == 0) { wcs[wid] = cs; wfs[wid] = fs; wfc[wid] = fc; wva[wid] = va; }
    __syncthreads();
    if (tid == 0) {
        cs = wcs[0] + wcs[1] + wcs[2] + wcs[3];
        fs = wfs[0] + wfs[1] + wfs[2] + wfs[3];
        fc = wfc[0] + wfc[1] + wfc[2] + wfc[3];
        va = wva[0] | wva[1] | wva[2] | wva[3];
        const float coarse = -cs / Bf;
        float fine;
        if (va) fine = (fc > 0) ? (fs / (float)fc) : 10.0f;
        else    fine = 1e-6f;
        out[0] = coarse + 1000.0f * fine;
        out[1] = coarse;
        out[2] = fine;
    }
}

// Launch helper: kernel with the PDL (programmatic stream serialization) attr.
template <typename... Args>
static void launch_pdl(void (*kern)(Args...), dim3 grid, dim3 block,
                       Args... args)
{
    cudaLaunchConfig_t cfg = {};
    cfg.gridDim = grid;
    cfg.blockDim = block;
    cudaLaunchAttribute attr[1];
    attr[0].id = cudaLaunchAttributeProgrammaticStreamSerialization;
    attr[0].val.programmaticStreamSerializationAllowed = 1;
    cfg.attrs = attr;
    cfg.numAttrs = 1;
    cudaLaunchKernelEx(&cfg, kern, args...);
}

extern "C" void kernel_launch(void* const* d_in, const int* in_sizes, int n_in,
                              void* d_out, int out_size)
{
    const float* cm       = (const float*)d_in[0];  // [B,L,L]
    const float* gt       = (const float*)d_in[1];  // [B,L,L]
    const float* samples0 = (const float*)d_in[2];  // [B,L,2]
    const float* samples1 = (const float*)d_in[3];  // [B,L,2]
    const float* mkpts0   = (const float*)d_in[4];  // [N,3]
    const float* mkpts1   = (const float*)d_in[5];  // [N,2]
    float* out = (float*)d_out;

    const long long BL = (long long)in_sizes[2] / 2;       // B*L
    const int L = (int)((long long)in_sizes[0] / BL);      // B*L*L / (B*L)
    const int B = (int)(BL / L);
    const int N = in_sizes[4] / 3;
    const int rows = B * L;
    const int nb = (rows + 255) / 256;   // build blocks
    const int pb = (N + 255) / 256;      // probe blocks

    mc_row_kernel<<<rows, 128>>>(cm, gt, L);
    launch_pdl(mc_build_kernel, dim3(nb), dim3(256), samples0, rows);
    launch_pdl(mc_probe_kernel, dim3(pb), dim3(256),
               samples0, samples1, mkpts0, mkpts1, L, N);
    launch_pdl(mc_finalize_kernel, dim3(1), dim3(128), out, nb, pb, (float)B);
}